// round 8
// baseline (speedup 1.0000x reference)
#include <cuda_runtime.h>
#include <cstdint>

#define BATCH 512
#define SEQ   512
#define OBS   103
#define HID   512
#define INP   105            // OBS + 2 fed-back pos
#define KTOT  617            // INP + HID
#define GAT   2048           // 4*HID
#define NBLK  128
#define NTHR  256
#define PITCH 34             // smem k-row pitch (floats, even -> 8B aligned pairs)
#define OFF_H (BATCH*SEQ*2)
#define OFF_C (OFF_H + BATCH*HID)
#define SA_FLOATS   (KTOT*PITCH + 2)      // 20980 (pad -> 16B alignment after)
#define W1S_FLOATS  (HID*64)              // 32768
#define HB_FLOATS   2048
#define SMEM_FLOATS (SA_FLOATS + W1S_FLOATS + HB_FLOATS + 256 + 64)
#define SMEM_BYTES  (SMEM_FLOATS*4)       // 224,464 B

typedef unsigned long long ull;

// ---- static device scratch (no allocation allowed) ----
__device__ __align__(16) float g_Wt[KTOT*GAT];   // k-major, gate-interleaved cols
__device__ __align__(16) float g_bias[GAT];      // b_ih+b_hh, permuted
__device__ __align__(16) float g_W1t[HID*64];    // layer1 weights, k-major
__device__ __align__(16) float g_W2t[64*16];     // layer2 weights, k-major
__device__ __align__(16) float g_hbuf[2][BATCH*HID];
__device__ __align__(16) float g_y[BATCH*2];
__device__ unsigned g_arrive;
__device__ volatile unsigned g_gen;

// ---- packed f32x2 helpers ----
__device__ __forceinline__ ull dup2(float x) {
    ull r; asm("mov.b64 %0, {%1, %1};" : "=l"(r) : "f"(x)); return r;
}
__device__ __forceinline__ float2 unpack2(ull v) {
    float lo, hi; asm("mov.b64 {%0, %1}, %2;" : "=f"(lo), "=f"(hi) : "l"(v));
    return make_float2(lo, hi);
}
__device__ __forceinline__ void fma2(ull &d, ull a, ull b) {
    asm("fma.rn.f32x2 %0, %1, %2, %0;" : "+l"(d) : "l"(a), "l"(b));
}

__device__ __forceinline__ float sigm(float x) { return 1.f / (1.f + __expf(-x)); }
__device__ __forceinline__ float tanh_(float x) {
    x = fminf(15.f, fmaxf(-15.f, x));
    float e = __expf(-2.f * x);
    return (1.f - e) / (1.f + e);
}

// ---- grid barrier: all 128 blocks co-resident -> spin is safe ----
__device__ __forceinline__ void grid_barrier(unsigned target) {
    __threadfence();
    __syncthreads();
    if (threadIdx.x == 0) {
        unsigned v = atomicAdd(&g_arrive, 1u);
        if (v == NBLK - 1) {
            g_arrive = 0;
            __threadfence();
            g_gen = target;
        } else {
            while (g_gen < target) { }   // tight spin on L2
        }
    }
    __syncthreads();
}

// ---- precompute: permuted transpose of W, combined bias, state init ----
__global__ void precompute_kernel(const float* __restrict__ W_ih,
                                  const float* __restrict__ W_hh,
                                  const float* __restrict__ b_ih,
                                  const float* __restrict__ b_hh,
                                  const float* __restrict__ hidden,
                                  const float* __restrict__ pos,
                                  const float* __restrict__ W1,
                                  const float* __restrict__ W2) {
    const int stride = gridDim.x * blockDim.x;
    const int i0 = blockIdx.x * blockDim.x + threadIdx.x;
    // Wt[k][col]; col = ubp*256 + ul*4 + g  <->  original row r = g*HID + ubp*64 + ul
    for (int idx = i0; idx < KTOT * GAT; idx += stride) {
        int k = idx >> 11, col = idx & 2047;
        int ubp = col >> 8, rem = col & 255, ul = rem >> 2, g = rem & 3;
        int r = g * HID + ubp * 64 + ul;
        g_Wt[idx] = (k < INP) ? W_ih[r * INP + k] : W_hh[r * HID + (k - INP)];
    }
    for (int col = i0; col < GAT; col += stride) {
        int ubp = col >> 8, rem = col & 255, ul = rem >> 2, g = rem & 3;
        int r = g * HID + ubp * 64 + ul;
        g_bias[col] = b_ih[r] + b_hh[r];
    }
    for (int idx = i0; idx < HID * 64; idx += stride) {
        int k = idx >> 6, u1 = idx & 63;
        g_W1t[idx] = W1[u1 * HID + k];
    }
    for (int idx = i0; idx < 64 * 16; idx += stride) {
        int k = idx >> 4, u2 = idx & 15;
        g_W2t[idx] = W2[u2 * 64 + k];
    }
    for (int idx = i0; idx < BATCH * HID; idx += stride) g_hbuf[0][idx] = hidden[idx];
    for (int idx = i0; idx < BATCH * 2; idx += stride)
        g_y[idx] = pos[(idx >> 1) * SEQ * 2 + (idx & 1)];   // pos[:,0,:]
    if (i0 == 0) { g_arrive = 0; g_gen = 0; }
}

// ---- persistent LSTM kernel ----
__global__ void __launch_bounds__(NTHR, 1)
lstm_persistent(const float* __restrict__ x,
                const float* __restrict__ cell,
                const float* __restrict__ b1,
                const float* __restrict__ b2,
                const float* __restrict__ W3, const float* __restrict__ b3,
                float* __restrict__ out) {
    extern __shared__ float sm[];
    float* sa    = sm;                     // staged input, k-major [KTOT][PITCH]
    float* w1s   = sm + SA_FLOATS;         // layer1 weights [512 k][64 u1]
    float* hbufS = w1s + W1S_FLOATS;       // MLP h, transposed [512 k][4 rows]
    float* y1s   = hbufS + HB_FLOATS;      // [4 r][64 u1]
    float* y2s   = y1s + 256;              // [4 r][16 u2]

    const int tid  = threadIdx.x;
    const int lane = tid & 31;
    const int wid  = tid >> 5;             // 0..7
    const int bt = blockIdx.x >> 3, ct = blockIdx.x & 7;
    const int tx = tid & 63, ty = tid >> 6;   // tx: unit, ty: 8-row group
    const int colbase = ct * 256 + tx * 4;    // one unit = 4 interleaved gates
    const int rowbase = bt * 32 + ty * 8;
    const int u       = ct * 64 + tx;         // global hidden unit
    const int mrowb   = blockIdx.x * 4;       // MLP rows for this block

    const float4 bA = *(const float4*)(g_bias + colbase);

    // cell state in registers: 8 batch rows x 1 unit
    float c[8];
#pragma unroll
    for (int b = 0; b < 8; b++) c[b] = cell[(size_t)(rowbase + b) * HID + u];

    unsigned bar = 0;

    // ---------- prologue: W1 to smem + stage step-0 input ----------
    for (int i = tid; i < W1S_FLOATS / 4; i += NTHR)
        ((float4*)w1s)[i] = ((const float4*)g_W1t)[i];
    {
        for (int r = wid; r < 32; r += 8) {
            int row = bt * 32 + r;
            const float* xr = x + (size_t)row * (SEQ * OBS);
            for (int k = lane; k < OBS; k += 32) sa[k * PITCH + r] = xr[k];
            const float* hr = &g_hbuf[0][(size_t)row * HID];
#pragma unroll
            for (int kk = 0; kk < 4; kk++) {
                float4 hv = *(const float4*)(hr + kk * 128 + lane * 4);
                float* d = sa + (INP + kk * 128 + lane * 4) * PITCH + r;
                d[0] = hv.x; d[PITCH] = hv.y; d[2 * PITCH] = hv.z; d[3 * PITCH] = hv.w;
            }
        }
        if (tid < 64) {
            int b = tid >> 1, j = tid & 1;
            sa[(OBS + j) * PITCH + b] = g_y[(bt * 32 + b) * 2 + j];
        }
        __syncthreads();
    }

    for (int t = 0; t < SEQ; t++) {
        // ---------- gates GEMM: 8 rows (4 pairs) x 4 gates per thread ----------
        ull acc[4][4];
#pragma unroll
        for (int p = 0; p < 4; p++) {
            acc[p][0] = dup2(bA.x);   // gate i, rows (2p,2p+1)
            acc[p][1] = dup2(bA.y);   // gate f
            acc[p][2] = dup2(bA.z);   // gate g
            acc[p][3] = dup2(bA.w);   // gate o
        }
        const float* wp = g_Wt + colbase;
        const float* ap = sa + ty * 8;

        float4 wbuf[4];
#pragma unroll
        for (int r = 0; r < 4; r++) wbuf[r] = *(const float4*)(wp + (size_t)r * GAT);

#pragma unroll 4
        for (int k = 0; k < KTOT; k++) {
            float4 w = wbuf[k & 3];
            const float* a = ap + k * PITCH;
            ull A0 = *(const ull*)(a);       // rows 0,1
            ull A1 = *(const ull*)(a + 2);   // rows 2,3
            ull A2 = *(const ull*)(a + 4);   // rows 4,5
            ull A3 = *(const ull*)(a + 6);   // rows 6,7
            int kp = k + 4;
            if (kp < KTOT) wbuf[k & 3] = *(const float4*)(wp + (size_t)kp * GAT);
            ull W0 = dup2(w.x), W1d = dup2(w.y), W2d = dup2(w.z), W3d = dup2(w.w);
            fma2(acc[0][0], A0, W0); fma2(acc[0][1], A0, W1d);
            fma2(acc[0][2], A0, W2d); fma2(acc[0][3], A0, W3d);
            fma2(acc[1][0], A1, W0); fma2(acc[1][1], A1, W1d);
            fma2(acc[1][2], A1, W2d); fma2(acc[1][3], A1, W3d);
            fma2(acc[2][0], A2, W0); fma2(acc[2][1], A2, W1d);
            fma2(acc[2][2], A2, W2d); fma2(acc[2][3], A2, W3d);
            fma2(acc[3][0], A3, W0); fma2(acc[3][1], A3, W1d);
            fma2(acc[3][2], A3, W2d); fma2(acc[3][3], A3, W3d);
        }

        // ---------- cell update (registers) + h write ----------
        const int wb = (t + 1) & 1;
#pragma unroll
        for (int p = 0; p < 4; p++) {
            float2 gi = unpack2(acc[p][0]);
            float2 gf = unpack2(acc[p][1]);
            float2 gg = unpack2(acc[p][2]);
            float2 go = unpack2(acc[p][3]);
            {
                float nc = sigm(gf.x) * c[2 * p] + sigm(gi.x) * tanh_(gg.x);
                float h  = sigm(go.x) * tanh_(nc);
                c[2 * p] = nc;
                int row = rowbase + 2 * p;
                __stcg(&g_hbuf[wb][(size_t)row * HID + u], h);
                if (t == SEQ - 1) {
                    out[OFF_H + (size_t)row * HID + u] = h;
                    out[OFF_C + (size_t)row * HID + u] = nc;
                }
            }
            {
                float nc = sigm(gf.y) * c[2 * p + 1] + sigm(gi.y) * tanh_(gg.y);
                float h  = sigm(go.y) * tanh_(nc);
                c[2 * p + 1] = nc;
                int row = rowbase + 2 * p + 1;
                __stcg(&g_hbuf[wb][(size_t)row * HID + u], h);
                if (t == SEQ - 1) {
                    out[OFF_H + (size_t)row * HID + u] = h;
                    out[OFF_C + (size_t)row * HID + u] = nc;
                }
            }
        }

        grid_barrier(++bar);   // h_t globally visible

        const float* hb = g_hbuf[wb];

        if (wid < 6) {
            // ---------- staging warps: stage x_{t+1}, h_t ----------
            if (t < SEQ - 1) {
                int tn = t + 1;
                for (int r = wid; r < 32; r += 6) {
                    int row = bt * 32 + r;
                    const float* xr = x + (size_t)row * (SEQ * OBS) + (size_t)tn * OBS;
                    for (int k = lane; k < OBS; k += 32) sa[k * PITCH + r] = xr[k];
                    const float* hr = hb + (size_t)row * HID;
#pragma unroll
                    for (int kk = 0; kk < 4; kk++) {
                        float4 hv = __ldcg((const float4*)(hr + kk * 128 + lane * 4));
                        float* d = sa + (INP + kk * 128 + lane * 4) * PITCH + r;
                        d[0] = hv.x; d[PITCH] = hv.y;
                        d[2 * PITCH] = hv.z; d[3 * PITCH] = hv.w;
                    }
                }
            }
        } else {
            // ---------- MLP warps (64 threads): full MLP for 4 rows ----------
            const int mtid = tid - 192;   // 0..63
            for (int i = mtid; i < 2048; i += 64) {
                int r = i >> 9, k = i & 511;
                hbufS[k * 4 + r] = __ldcg(&hb[(size_t)(mrowb + r) * HID + k]);
            }
            asm volatile("bar.sync 1, 64;" ::: "memory");
            {   // layer 1: thread = u1, 4 rows
                int u1 = mtid;
                float a0 = 0.f, a1 = 0.f, a2 = 0.f, a3 = 0.f;
#pragma unroll 16
                for (int k = 0; k < 512; k++) {
                    float w = w1s[k * 64 + u1];
                    float4 hv = *(const float4*)(hbufS + k * 4);
                    a0 = fmaf(hv.x, w, a0);
                    a1 = fmaf(hv.y, w, a1);
                    a2 = fmaf(hv.z, w, a2);
                    a3 = fmaf(hv.w, w, a3);
                }
                float bb = __ldg(&b1[u1]);
                y1s[u1]        = fmaxf(a0 + bb, 0.f);
                y1s[64 + u1]   = fmaxf(a1 + bb, 0.f);
                y1s[128 + u1]  = fmaxf(a2 + bb, 0.f);
                y1s[192 + u1]  = fmaxf(a3 + bb, 0.f);
            }
            asm volatile("bar.sync 1, 64;" ::: "memory");
            {   // layer 2: thread = (r,u2)
                int r = mtid >> 4, u2 = mtid & 15;
                const float* yr = y1s + r * 64;
                float v = __ldg(&b2[u2]);
#pragma unroll
                for (int kk = 0; kk < 64; kk++)
                    v = fmaf(yr[kk], __ldg(&g_W2t[kk * 16 + u2]), v);
                y2s[r * 16 + u2] = fmaxf(v, 0.f);
            }
            asm volatile("bar.sync 1, 64;" ::: "memory");
            if (mtid < 8) {   // layer 3: 16 -> 2
                int r = mtid >> 1, j = mtid & 1;
                const float* yr = y2s + r * 16;
                float v = __ldg(&b3[j]);
#pragma unroll
                for (int kk = 0; kk < 16; kk++)
                    v = fmaf(yr[kk], __ldg(&W3[j * 16 + kk]), v);
                v = fmaxf(v, 0.f);
                int row = mrowb + r;
                __stcg(&g_y[row * 2 + j], v);
                out[(size_t)row * SEQ * 2 + (size_t)t * 2 + j] = v;
            }
        }

        if (t < SEQ - 1) {
            grid_barrier(++bar);   // y_t globally visible
            if (tid < 64) {        // patch fed-back pos into staged input
                int b = tid >> 1, j = tid & 1;
                sa[(OBS + j) * PITCH + b] = __ldcg(&g_y[(bt * 32 + b) * 2 + j]);
            }
            __syncthreads();
        }
    }
}

extern "C" void kernel_launch(void* const* d_in, const int* in_sizes, int n_in,
                              void* d_out, int out_size) {
    const float* x      = (const float*)d_in[0];
    const float* pos    = (const float*)d_in[1];
    const float* hidden = (const float*)d_in[2];
    const float* cell   = (const float*)d_in[3];
    const float* W_ih   = (const float*)d_in[4];
    const float* W_hh   = (const float*)d_in[5];
    const float* b_ih   = (const float*)d_in[6];
    const float* b_hh   = (const float*)d_in[7];
    const float* W1     = (const float*)d_in[8];
    const float* b1     = (const float*)d_in[9];
    const float* W2     = (const float*)d_in[10];
    const float* b2     = (const float*)d_in[11];
    const float* W3     = (const float*)d_in[12];
    const float* b3     = (const float*)d_in[13];
    float* out = (float*)d_out;

    cudaFuncSetAttribute((const void*)lstm_persistent,
                         cudaFuncAttributeMaxDynamicSharedMemorySize, SMEM_BYTES);

    precompute_kernel<<<512, 256>>>(W_ih, W_hh, b_ih, b_hh, hidden, pos, W1, W2);
    lstm_persistent<<<NBLK, NTHR, SMEM_BYTES>>>(x, cell, b1, b2, W3, b3, out);
}